// round 14
// baseline (speedup 1.0000x reference)
#include <cuda_runtime.h>
#include <cuda_fp16.h>
#include <math.h>
#include <stdint.h>

// ---------------- problem constants ----------------
#define T_TOK   32768
#define D_DIM   1024
#define E_EXP   16
#define I_DIM   2816
#define TWO_I   5632
#define TK_SLOTS 65536
#define CAP     5120
#define NB      64
#define SPB     1024
#define RBLK    1024

// ---------------- scratch (device globals; no allocs) ----------------
__device__ __half g_xh[(size_t)E_EXP * CAP * D_DIM];
__device__ __half g_acth[(size_t)E_EXP * CAP * I_DIM];
__device__ __half g_eouth[(size_t)E_EXP * CAP * D_DIM];
__device__ __half g_wug_th[(size_t)E_EXP * TWO_I * D_DIM];
__device__ __half g_wdn_th[(size_t)E_EXP * D_DIM * I_DIM];
__device__ int   g_sel[TK_SLOTS];
__device__ float g_comb[TK_SLOTS];
__device__ int   g_poslocal[TK_SLOTS];
__device__ int   g_slot[TK_SLOTS];
__device__ int   g_blkCnt[NB][E_EXP];
__device__ int   g_blkOff[NB][E_EXP];
__device__ int   g_cnt[E_EXP];
__device__ float g_rp[RBLK][E_EXP];
__device__ float g_rz[RBLK];
__device__ int   g_posDone;

// ---------------- helpers ----------------
__device__ __forceinline__ void mma_f16(float* c,
                                        uint32_t a0, uint32_t a1, uint32_t a2, uint32_t a3,
                                        uint32_t b0, uint32_t b1) {
    asm volatile("mma.sync.aligned.m16n8k16.row.col.f32.f16.f16.f32 "
                 "{%0,%1,%2,%3}, {%4,%5,%6,%7}, {%8,%9}, {%0,%1,%2,%3};"
                 : "+f"(c[0]), "+f"(c[1]), "+f"(c[2]), "+f"(c[3])
                 : "r"(a0), "r"(a1), "r"(a2), "r"(a3), "r"(b0), "r"(b1));
}
__device__ __forceinline__ uint32_t pack_h2(float a, float b) {
    __half2 h = __floats2half2_rn(a, b);
    return *reinterpret_cast<uint32_t*>(&h);
}
__device__ __forceinline__ uint32_t smem_u32(const void* p) {
    uint32_t a;
    asm("{ .reg .u64 t; cvta.to.shared.u64 t, %1; cvt.u32.u64 %0, t; }" : "=r"(a) : "l"(p));
    return a;
}
#define LDSM_X4(r0_, r1_, r2_, r3_, addr_) \
    asm volatile("ldmatrix.sync.aligned.m8n8.x4.shared.b16 {%0,%1,%2,%3}, [%4];" \
                 : "=r"(r0_), "=r"(r1_), "=r"(r2_), "=r"(r3_) : "r"(addr_))
#define CP_ASYNC16(dst_u32, src_ptr) \
    asm volatile("cp.async.cg.shared.global [%0], [%1], 16;" :: "r"(dst_u32), "l"(src_ptr))
#define CP_COMMIT()  asm volatile("cp.async.commit_group;")
#define CP_WAIT0()   asm volatile("cp.async.wait_group 0;")

// ---------------- router ----------------
#define R_PAD 20
#define R_SMEM_BYTES (D_DIM * R_PAD * 4)
__global__ __launch_bounds__(256) void router_kernel(const float* __restrict__ x,
                                                     const float* __restrict__ router) {
    extern __shared__ float rs[];
    __shared__ float s_p[E_EXP];
    __shared__ float s_z2;
    const int tid  = threadIdx.x;
    const int wid  = tid >> 5;
    const int lane = tid & 31;
    if (tid < E_EXP) s_p[tid] = 0.f;
    if (tid == 0)    s_z2 = 0.f;
    for (int t = tid; t < D_DIM * E_EXP; t += 256)
        rs[(t >> 4) * R_PAD + (t & 15)] = router[t];
    __syncthreads();

    #pragma unroll
    for (int j = 0; j < 4; j++) {
        const int tok = blockIdx.x * 32 + wid * 4 + j;
        const float* xr = x + (size_t)tok * D_DIM;
        float acc[E_EXP];
        #pragma unroll
        for (int e = 0; e < E_EXP; e++) acc[e] = 0.f;
        for (int i = lane; i < D_DIM; i += 32) {
            const float xv = xr[i];
            const float4* rp = (const float4*)&rs[i * R_PAD];
            float4 r0 = rp[0], r1 = rp[1], r2 = rp[2], r3 = rp[3];
            acc[0]  += xv * r0.x; acc[1]  += xv * r0.y; acc[2]  += xv * r0.z; acc[3]  += xv * r0.w;
            acc[4]  += xv * r1.x; acc[5]  += xv * r1.y; acc[6]  += xv * r1.z; acc[7]  += xv * r1.w;
            acc[8]  += xv * r2.x; acc[9]  += xv * r2.y; acc[10] += xv * r2.z; acc[11] += xv * r2.w;
            acc[12] += xv * r3.x; acc[13] += xv * r3.y; acc[14] += xv * r3.z; acc[15] += xv * r3.w;
        }
        #pragma unroll
        for (int off = 16; off; off >>= 1) {
            #pragma unroll
            for (int e = 0; e < E_EXP; e++)
                acc[e] += __shfl_xor_sync(0xffffffffu, acc[e], off);
        }
        float m = acc[0];
        #pragma unroll
        for (int e = 1; e < E_EXP; e++) m = fmaxf(m, acc[e]);
        float se = 0.f;
        #pragma unroll
        for (int e = 0; e < E_EXP; e++) se += expf(acc[e] - m);
        const float z = m + logf(se);

        int i1 = 0; float l1 = acc[0];
        #pragma unroll
        for (int e = 1; e < E_EXP; e++) if (acc[e] > l1) { l1 = acc[e]; i1 = e; }
        int i2 = -1; float l2 = -1e30f;
        #pragma unroll
        for (int e = 0; e < E_EXP; e++)
            if (e != i1 && acc[e] > l2) { l2 = acc[e]; i2 = e; }

        const float q  = expf(l2 - l1);
        if (lane == 0) {
            g_sel[2 * tok]     = i1;
            g_sel[2 * tok + 1] = i2;
            g_comb[2 * tok]     = 1.f / (1.f + q);
            g_comb[2 * tok + 1] = q / (1.f + q);
            atomicAdd(&s_z2, z * z);
        }
        if (lane < E_EXP) atomicAdd(&s_p[lane], expf(acc[lane] - m) / se);
    }
    __syncthreads();
    if (tid < E_EXP) g_rp[blockIdx.x][tid] = s_p[tid];
    if (tid == 0)    g_rz[blockIdx.x] = s_z2;
}

// ---------------- ordered per-expert rank + fused last-block scan ----------------
__global__ void pos_kernel() {
    __shared__ int warpCnt[8][E_EXP];
    __shared__ int running[E_EXP];
    __shared__ int s_last;
    const int tid  = threadIdx.x;
    const int wid  = tid >> 5;
    const int lane = tid & 31;
    if (tid < E_EXP) running[tid] = 0;
    __syncthreads();

    const int base = blockIdx.x * SPB;
    for (int it = 0; it < SPB / 256; it++) {
        const int s = base + it * 256 + tid;
        const int e = g_sel[s];
        unsigned peers = __match_any_sync(0xffffffffu, e);
        const int rank = __popc(peers & ((1u << lane) - 1u));
        if (lane < E_EXP) warpCnt[wid][lane] = 0;
        __syncwarp();
        if (rank == 0) warpCnt[wid][e] = __popc(peers);
        __syncthreads();
        int off = running[e] + rank;
        for (int w = 0; w < wid; w++) off += warpCnt[w][e];
        g_poslocal[s] = off;
        __syncthreads();
        if (tid < E_EXP) {
            int tot = 0;
            #pragma unroll
            for (int w = 0; w < 8; w++) tot += warpCnt[w][tid];
            running[tid] += tot;
        }
        __syncthreads();
    }
    if (tid < E_EXP) g_blkCnt[blockIdx.x][tid] = running[tid];
    __syncthreads();
    if (tid == 0) {
        __threadfence();
        s_last = (atomicAdd(&g_posDone, 1) == NB - 1) ? 1 : 0;
    }
    __syncthreads();
    if (s_last) {
        if (tid < E_EXP) {
            int run = 0;
            for (int b = 0; b < NB; b++) {
                g_blkOff[b][tid] = run;
                run += g_blkCnt[b][tid];
            }
            g_cnt[tid] = run;
        }
        __syncthreads();
        if (tid == 0) { g_posDone = 0; __threadfence(); }
    }
}

// ---------------- prep: scatter + both weight transposes ----------------
#define SC_BLOCKS 8192
#define UG_BX (TWO_I / 32)
#define UG_BY (D_DIM / 32)
#define UG_BLOCKS (UG_BX * UG_BY * E_EXP)
#define DN_BX (D_DIM / 32)
#define DN_BY (I_DIM / 32)
#define DN_BLOCKS (DN_BX * DN_BY * E_EXP)
#define PREP_BLOCKS (SC_BLOCKS + UG_BLOCKS + DN_BLOCKS)

__global__ __launch_bounds__(256) void prep_kernel(const float* __restrict__ x,
                                                   const float* __restrict__ w_ug,
                                                   const float* __restrict__ w_dn) {
    __shared__ float tile[32][33];
    const int bid = blockIdx.x;
    const int tid = threadIdx.x;

    if (bid < SC_BLOCKS) {
        const int gwarp = (bid * 256 + tid) >> 5;
        const int lane  = tid & 31;
        const int e   = g_sel[gwarp];
        const int pos = g_poslocal[gwarp] + g_blkOff[gwarp / SPB][e];
        int slot = -1;
        if (pos < CAP) {
            slot = e * CAP + pos;
            const float4* src = (const float4*)(x + (size_t)(gwarp >> 1) * D_DIM);
            uint2* dst = (uint2*)(g_xh + (size_t)slot * D_DIM);
            #pragma unroll
            for (int i = 0; i < 8; i++) {
                float4 v = src[lane + 32 * i];
                dst[lane + 32 * i] = make_uint2(pack_h2(v.x, v.y), pack_h2(v.z, v.w));
            }
        }
        if (lane == 0) g_slot[gwarp] = slot;
        return;
    }

    const int tx = tid & 31, ty = tid >> 5;
    if (bid < SC_BLOCKS + UG_BLOCKS) {
        const int t = bid - SC_BLOCKS;
        const int z = t / (UG_BX * UG_BY);
        const int rem = t % (UG_BX * UG_BY);
        const int bx = rem % UG_BX, by = rem / UG_BX;
        const float* S = w_ug + (size_t)z * D_DIM * TWO_I;
        __half* Dp = g_wug_th + (size_t)z * TWO_I * D_DIM;
        const int c0 = bx * 32, r0 = by * 32;
        #pragma unroll
        for (int i = 0; i < 32; i += 8)
            tile[ty + i][tx] = S[(size_t)(r0 + ty + i) * TWO_I + (c0 + tx)];
        __syncthreads();
        #pragma unroll
        for (int i = 0; i < 32; i += 8) {
            const int c = c0 + ty + i;
            int pcol;
            if (c < I_DIM) pcol = 16 * (c >> 3) + (c & 7);
            else { const int j = c - I_DIM; pcol = 16 * (j >> 3) + 8 + (j & 7); }
            Dp[(size_t)pcol * D_DIM + (r0 + tx)] = __float2half_rn(tile[tx][ty + i]);
        }
    } else {
        const int t = bid - SC_BLOCKS - UG_BLOCKS;
        const int z = t / (DN_BX * DN_BY);
        const int rem = t % (DN_BX * DN_BY);
        const int bx = rem % DN_BX, by = rem / DN_BX;
        const float* S = w_dn + (size_t)z * I_DIM * D_DIM;
        __half* Dp = g_wdn_th + (size_t)z * D_DIM * I_DIM;
        const int c0 = bx * 32, r0 = by * 32;
        #pragma unroll
        for (int i = 0; i < 32; i += 8)
            tile[ty + i][tx] = S[(size_t)(r0 + ty + i) * D_DIM + (c0 + tx)];
        __syncthreads();
        #pragma unroll
        for (int i = 0; i < 32; i += 8)
            Dp[(size_t)(c0 + ty + i) * I_DIM + (r0 + tx)] = __float2half_rn(tile[tx][ty + i]);
    }
}

// ---------------- fp16 mma GEMM: CTA 256x128, 512 threads, 2-stage, K-chunk 128 ----------
// SU = 68 u32 (64 data + 4 pad); A tile 256 rows, B tile 128 rows.
// 2 buffers x (A+B) = 208896 B smem. Chunk boundaries: G1 8, G2 22.
#define SU 68
#define A_TILE_U (256 * SU)
#define B_TILE_U (128 * SU)
#define BUF_U  (A_TILE_U + B_TILE_U)
#define HG_SMEM (2 * BUF_U * 4)           // 208896 bytes

template <int Kdim, int Ndim, int WHICH>
__global__ __launch_bounds__(512, 1)
void hgemm_kernel(const __half* __restrict__ Wt) {
    const int e   = blockIdx.z;
    const int cnt = g_cnt[e];
    const int m0  = blockIdx.y * 256;
    if (m0 >= cnt) return;
    const int n0  = blockIdx.x * 128;

    const __half* __restrict__ Ah = ((WHICH == 1) ? g_xh : g_acth)
                                    + (size_t)e * CAP * Kdim + (size_t)m0 * Kdim;
    const __half* __restrict__ Bh = Wt + (size_t)e * Ndim * Kdim + (size_t)n0 * Kdim;

    extern __shared__ uint32_t smem[];
    const uint32_t smem_base = smem_u32(smem);

    const int tid  = threadIdx.x;
    const int lane = tid & 31;
    const int wid  = tid >> 5;
    const int warp_m = (wid >> 2) * 64;
    const int warp_n = (wid & 3) * 32;
    const int g  = lane >> 2;
    const int t4 = lane & 3;

    float acc[4][4][4];
    #pragma unroll
    for (int i = 0; i < 4; i++)
        #pragma unroll
        for (int j = 0; j < 4; j++)
            #pragma unroll
            for (int q = 0; q < 4; q++) acc[i][j][q] = 0.f;

    // cp.async maps (per chunk): A 256 rows x 16 pieces(16B) = 8/thread;
    //                            B 128 rows x 16 pieces      = 4/thread
    const int aSRow = tid >> 1;
    const int aJ0   = (tid & 1) * 8;          // 0 or 8
    const int bSRow = tid >> 2;
    const int bJ0   = (tid & 3) * 4;          // 0,4,8,12

    const int aRow = warp_m + (lane & 15);
    const int aOff = 4 * (lane >> 4);
    const int bRow = warp_n + 8 * ((lane >> 4) & 1) + (lane & 7);
    const int bOff = 4 * ((lane >> 3) & 1);
    const uint32_t aBase = smem_base + (uint32_t)(aRow * SU + aOff) * 4u;
    const uint32_t bBase = smem_base + (uint32_t)(A_TILE_U + bRow * SU + bOff) * 4u;

    const int NC = Kdim / 128;

    #define HG_ISSUE(c_) do {                                                     \
        const uint32_t dstA = smem_base + (uint32_t)(((c_) & 1) * BUF_U) * 4u;    \
        const uint32_t dstB = dstA + (uint32_t)A_TILE_U * 4u;                     \
        const int k0_ = (c_) * 128;                                               \
        _Pragma("unroll")                                                         \
        for (int i_ = 0; i_ < 8; i_++) {                                          \
            const int j_ = aJ0 + i_;                                              \
            CP_ASYNC16(dstA + (uint32_t)(aSRow * SU + j_ * 4) * 4u,               \
                       Ah + (size_t)aSRow * Kdim + k0_ + j_ * 8);                 \
        }                                                                         \
        _Pragma("unroll")                                                         \
        for (int i_ = 0; i_ < 4; i_++) {                                          \
            const int j_ = bJ0 + i_;                                              \
            CP_ASYNC16(dstB + (uint32_t)(bSRow * SU + j_ * 4) * 4u,               \
                       Bh + (size_t)bSRow * Kdim + k0_ + j_ * 8);                 \
        }                                                                         \
        CP_COMMIT();                                                              \
    } while (0)

    HG_ISSUE(0);

    for (int c = 0; c < NC; c++) {
        CP_WAIT0();
        __syncthreads();
        if (c + 1 < NC) HG_ISSUE(c + 1);
        const uint32_t bufOff = (uint32_t)((c & 1) * BUF_U) * 4u;

        #pragma unroll
        for (int ks = 0; ks < 8; ks++) {
            uint32_t bf[4][2];
            #pragma unroll
            for (int p = 0; p < 2; p++) {
                LDSM_X4(bf[2 * p][0], bf[2 * p][1], bf[2 * p + 1][0], bf[2 * p + 1][1],
                        bBase + bufOff + (uint32_t)(p * 16 * SU * 4 + ks * 32));
            }
            #pragma unroll
            for (int mf = 0; mf < 4; mf++) {
                uint32_t a0, a1, a2, a3;
                LDSM_X4(a0, a1, a2, a3,
                        aBase + bufOff + (uint32_t)(mf * 16 * SU * 4 + ks * 32));
                #pragma unroll
                for (int nf = 0; nf < 4; nf++)
                    mma_f16(acc[mf][nf], a0, a1, a2, a3, bf[nf][0], bf[nf][1]);
            }
        }
    }

    if (WHICH == 1) {
        __half* Ao = g_acth + (size_t)(e * CAP + m0) * I_DIM;
        #pragma unroll
        for (int mf = 0; mf < 4; mf++) {
            const int row = warp_m + mf * 16 + g;
            #pragma unroll
            for (int pr = 0; pr < 2; pr++) {
                const int j = n0 / 2 + ((wid & 3) * 2 + pr) * 8 + t4 * 2;
                const float* gg = acc[mf][2 * pr];
                const float* uu = acc[mf][2 * pr + 1];
                const float a0 = gg[0] / (1.f + expf(-gg[0])) * uu[0];
                const float a1 = gg[1] / (1.f + expf(-gg[1])) * uu[1];
                const float a2 = gg[2] / (1.f + expf(-gg[2])) * uu[2];
                const float a3 = gg[3] / (1.f + expf(-gg[3])) * uu[3];
                *(uint32_t*)(Ao + (size_t)row * I_DIM + j)       = pack_h2(a0, a1);
                *(uint32_t*)(Ao + (size_t)(row + 8) * I_DIM + j) = pack_h2(a2, a3);
            }
        }
    } else {
        __half* Co = g_eouth + (size_t)(e * CAP + m0) * Ndim + n0;
        #pragma unroll
        for (int mf = 0; mf < 4; mf++) {
            const int row = warp_m + mf * 16 + g;
            #pragma unroll
            for (int nf = 0; nf < 4; nf++) {
                const int col = warp_n + nf * 8 + t4 * 2;
                *(uint32_t*)(Co + (size_t)row * Ndim + col) =
                    pack_h2(acc[mf][nf][0], acc[mf][nf][1]);
                *(uint32_t*)(Co + (size_t)(row + 8) * Ndim + col) =
                    pack_h2(acc[mf][nf][2], acc[mf][nf][3]);
            }
        }
    }
}

// ---------------- gather + combine (fp16 expert outputs, uint4 loads) ----------------
__global__ void gather_kernel(float* __restrict__ out) {
    const int t    = (blockIdx.x * blockDim.x + threadIdx.x) >> 5;
    const int lane = threadIdx.x & 31;
    if (t >= T_TOK) return;
    const int s0 = 2 * t, s1 = s0 + 1;
    const int sl0 = g_slot[s0], sl1 = g_slot[s1];
    const float w0 = g_comb[s0], w1 = g_comb[s1];
    const uint4* r0 = (sl0 >= 0) ? (const uint4*)(g_eouth + (size_t)sl0 * D_DIM) : nullptr;
    const uint4* r1 = (sl1 >= 0) ? (const uint4*)(g_eouth + (size_t)sl1 * D_DIM) : nullptr;
    float4* orow = (float4*)(out + (size_t)t * D_DIM);
    #pragma unroll
    for (int ii = 0; ii < 4; ii++) {
        const int i = lane + 32 * ii;     // uint4 index: 8 halves
        float r[8];
        #pragma unroll
        for (int q = 0; q < 8; q++) r[q] = 0.f;
        if (r0) {
            uint4 v = r0[i];
            float2 p0 = __half22float2(*(__half2*)&v.x);
            float2 p1 = __half22float2(*(__half2*)&v.y);
            float2 p2 = __half22float2(*(__half2*)&v.z);
            float2 p3 = __half22float2(*(__half2*)&v.w);
            r[0] += w0 * p0.x; r[1] += w0 * p0.y; r[2] += w0 * p1.x; r[3] += w0 * p1.y;
            r[4] += w0 * p2.x; r[5] += w0 * p2.y; r[6] += w0 * p3.x; r[7] += w0 * p3.y;
        }
        if (r1) {
            uint4 v = r1[i];
            float2 p0 = __half22float2(*(__half2*)&v.x);
            float2 p1 = __half22float2(*(__half2*)&v.y);
            float2 p2 = __half22float2(*(__half2*)&v.z);
            float2 p3 = __half22float2(*(__half2*)&v.w);
            r[0] += w1 * p0.x; r[1] += w1 * p0.y; r[2] += w1 * p1.x; r[3] += w1 * p1.y;
            r[4] += w1 * p2.x; r[5] += w1 * p2.y; r[6] += w1 * p3.x; r[7] += w1 * p3.y;
        }
        orow[2 * i]     = make_float4(r[0], r[1], r[2], r[3]);
        orow[2 * i + 1] = make_float4(r[4], r[5], r[6], r[7]);
    }
}

// ---------------- final scalars ----------------
__global__ __launch_bounds__(256) void finalize_kernel(float* __restrict__ out) {
    __shared__ float sp[16][E_EXP];
    __shared__ float sz[256];
    __shared__ float s_sum[E_EXP];
    const int tid = threadIdx.x;
    const int e = tid & 15, p = tid >> 4;

    float s = 0.f;
    for (int b = p; b < RBLK; b += 16) s += g_rp[b][e];
    sp[p][e] = s;
    float zz = 0.f;
    for (int b = tid; b < RBLK; b += 256) zz += g_rz[b];
    sz[tid] = zz;
    __syncthreads();

    if (tid < E_EXP) {
        float tsum = 0.f;
        #pragma unroll
        for (int p2 = 0; p2 < 16; p2++) tsum += sp[p2][tid];
        s_sum[tid] = tsum;
    }
    if (tid == 16) {
        float t = 0.f;
        for (int i = 0; i < 256; i++) t += sz[i];
        sz[0] = t;
    }
    __syncthreads();

    const size_t base = (size_t)T_TOK * D_DIM;
    if (tid < E_EXP) out[base + tid] = (float)g_cnt[tid];
    if (tid == 0) {
        float total = 0.f;
        #pragma unroll
        for (int ee = 0; ee < E_EXP; ee++) total += (float)g_cnt[ee];
        total = fmaxf(total, 1.f);
        float ent = 0.f, lb = 0.f;
        #pragma unroll
        for (int ee = 0; ee < E_EXP; ee++) {
            float f = (float)g_cnt[ee] / total;
            ent -= f * logf(f + 1e-6f);
            lb  += (f * 2.0f) * (s_sum[ee] / (float)T_TOK);
        }
        lb *= (float)E_EXP;
        out[base + 16] = ent;
        out[base + 17] = lb;
        out[base + 18] = sz[0] / (float)T_TOK;
    }
}

// ---------------- launch ----------------
extern "C" void kernel_launch(void* const* d_in, const int* in_sizes, int n_in,
                              void* d_out, int out_size) {
    const float* x      = (const float*)d_in[0];
    const float* router = (const float*)d_in[1];
    const float* w_ug   = (const float*)d_in[2];
    const float* w_dn   = (const float*)d_in[3];
    float* out = (float*)d_out;

    __half *wug_t = nullptr, *wdn_t = nullptr;
    cudaGetSymbolAddress((void**)&wug_t, g_wug_th);
    cudaGetSymbolAddress((void**)&wdn_t, g_wdn_th);

    static bool attr_done = false;
    if (!attr_done) {
        cudaFuncSetAttribute(router_kernel, cudaFuncAttributeMaxDynamicSharedMemorySize, R_SMEM_BYTES);
        cudaFuncSetAttribute(hgemm_kernel<D_DIM, TWO_I, 1>,
                             cudaFuncAttributeMaxDynamicSharedMemorySize, HG_SMEM);
        cudaFuncSetAttribute(hgemm_kernel<I_DIM, D_DIM, 2>,
                             cudaFuncAttributeMaxDynamicSharedMemorySize, HG_SMEM);
        attr_done = true;
    }

    router_kernel<<<RBLK, 256, R_SMEM_BYTES>>>(x, router);          // 0
    pos_kernel<<<NB, 256>>>();                                      // 1
    prep_kernel<<<PREP_BLOCKS, 256>>>(x, w_ug, w_dn);               // 2
    hgemm_kernel<D_DIM, TWO_I, 1>                                   // 3 (ncu)
        <<<dim3(TWO_I / 128, CAP / 256, E_EXP), 512, HG_SMEM>>>(wug_t);
    hgemm_kernel<I_DIM, D_DIM, 2>                                   // 4
        <<<dim3(D_DIM / 128, CAP / 256, E_EXP), 512, HG_SMEM>>>(wdn_t);
    gather_kernel<<<T_TOK / 8, 256>>>(out);                         // 5
    finalize_kernel<<<1, 256>>>(out);                               // 6
}

// round 15
// speedup vs baseline: 1.1452x; 1.1452x over previous
#include <cuda_runtime.h>
#include <cuda_fp16.h>
#include <math.h>
#include <stdint.h>

// ---------------- problem constants ----------------
#define T_TOK   32768
#define D_DIM   1024
#define E_EXP   16
#define I_DIM   2816
#define TWO_I   5632
#define TK_SLOTS 65536
#define CAP     5120
#define NB      64
#define SPB     1024
#define RBLK    512           // router blocks: 64 tokens each

// ---------------- scratch (device globals; no allocs) ----------------
__device__ __half g_xh[(size_t)E_EXP * CAP * D_DIM];
__device__ __half g_acth[(size_t)E_EXP * CAP * I_DIM];
__device__ __half g_eouth[(size_t)E_EXP * CAP * D_DIM];
__device__ __half g_wug_th[(size_t)E_EXP * TWO_I * D_DIM];
__device__ __half g_wdn_th[(size_t)E_EXP * D_DIM * I_DIM];
__device__ int   g_sel[TK_SLOTS];
__device__ float g_comb[TK_SLOTS];
__device__ int   g_poslocal[TK_SLOTS];
__device__ int   g_slot[TK_SLOTS];
__device__ int   g_blkCnt[NB][E_EXP];
__device__ int   g_blkOff[NB][E_EXP];
__device__ int   g_cnt[E_EXP];
__device__ float g_rp[RBLK][E_EXP];
__device__ float g_rz[RBLK];
__device__ int   g_posDone;

// ---------------- helpers ----------------
__device__ __forceinline__ void mma_f16(float* c,
                                        uint32_t a0, uint32_t a1, uint32_t a2, uint32_t a3,
                                        uint32_t b0, uint32_t b1) {
    asm volatile("mma.sync.aligned.m16n8k16.row.col.f32.f16.f16.f32 "
                 "{%0,%1,%2,%3}, {%4,%5,%6,%7}, {%8,%9}, {%0,%1,%2,%3};"
                 : "+f"(c[0]), "+f"(c[1]), "+f"(c[2]), "+f"(c[3])
                 : "r"(a0), "r"(a1), "r"(a2), "r"(a3), "r"(b0), "r"(b1));
}
__device__ __forceinline__ uint32_t pack_h2(float a, float b) {
    __half2 h = __floats2half2_rn(a, b);
    return *reinterpret_cast<uint32_t*>(&h);
}
__device__ __forceinline__ uint32_t smem_u32(const void* p) {
    uint32_t a;
    asm("{ .reg .u64 t; cvta.to.shared.u64 t, %1; cvt.u32.u64 %0, t; }" : "=r"(a) : "l"(p));
    return a;
}
#define LDSM_X4(r0_, r1_, r2_, r3_, addr_) \
    asm volatile("ldmatrix.sync.aligned.m8n8.x4.shared.b16 {%0,%1,%2,%3}, [%4];" \
                 : "=r"(r0_), "=r"(r1_), "=r"(r2_), "=r"(r3_) : "r"(addr_))
#define CP_ASYNC16(dst_u32, src_ptr) \
    asm volatile("cp.async.cg.shared.global [%0], [%1], 16;" :: "r"(dst_u32), "l"(src_ptr))
#define CP_COMMIT()  asm volatile("cp.async.commit_group;")
#define CP_WAIT1()   asm volatile("cp.async.wait_group 1;")

// ---------------- router: SMEM-cached weights, 64 tokens/block ----------------
#define R_PAD 20
#define R_SMEM_BYTES (D_DIM * R_PAD * 4)
__global__ __launch_bounds__(256) void router_kernel(const float* __restrict__ x,
                                                     const float* __restrict__ router) {
    extern __shared__ float rs[];
    __shared__ float s_p[E_EXP];
    __shared__ float s_z2;
    const int tid  = threadIdx.x;
    const int wid  = tid >> 5;
    const int lane = tid & 31;
    if (tid < E_EXP) s_p[tid] = 0.f;
    if (tid == 0)    s_z2 = 0.f;
    for (int t = tid; t < D_DIM * E_EXP; t += 256)
        rs[(t >> 4) * R_PAD + (t & 15)] = router[t];
    __syncthreads();

    #pragma unroll
    for (int j = 0; j < 8; j++) {
        const int tok = blockIdx.x * 64 + wid * 8 + j;
        const float* xr = x + (size_t)tok * D_DIM;
        float acc[E_EXP];
        #pragma unroll
        for (int e = 0; e < E_EXP; e++) acc[e] = 0.f;
        for (int i = lane; i < D_DIM; i += 32) {
            const float xv = xr[i];
            const float4* rp = (const float4*)&rs[i * R_PAD];
            float4 r0 = rp[0], r1 = rp[1], r2 = rp[2], r3 = rp[3];
            acc[0]  += xv * r0.x; acc[1]  += xv * r0.y; acc[2]  += xv * r0.z; acc[3]  += xv * r0.w;
            acc[4]  += xv * r1.x; acc[5]  += xv * r1.y; acc[6]  += xv * r1.z; acc[7]  += xv * r1.w;
            acc[8]  += xv * r2.x; acc[9]  += xv * r2.y; acc[10] += xv * r2.z; acc[11] += xv * r2.w;
            acc[12] += xv * r3.x; acc[13] += xv * r3.y; acc[14] += xv * r3.z; acc[15] += xv * r3.w;
        }
        #pragma unroll
        for (int off = 16; off; off >>= 1) {
            #pragma unroll
            for (int e = 0; e < E_EXP; e++)
                acc[e] += __shfl_xor_sync(0xffffffffu, acc[e], off);
        }
        float m = acc[0];
        #pragma unroll
        for (int e = 1; e < E_EXP; e++) m = fmaxf(m, acc[e]);
        float se = 0.f;
        #pragma unroll
        for (int e = 0; e < E_EXP; e++) se += expf(acc[e] - m);
        const float z = m + logf(se);

        int i1 = 0; float l1 = acc[0];
        #pragma unroll
        for (int e = 1; e < E_EXP; e++) if (acc[e] > l1) { l1 = acc[e]; i1 = e; }
        int i2 = -1; float l2 = -1e30f;
        #pragma unroll
        for (int e = 0; e < E_EXP; e++)
            if (e != i1 && acc[e] > l2) { l2 = acc[e]; i2 = e; }

        const float q  = expf(l2 - l1);
        if (lane == 0) {
            g_sel[2 * tok]     = i1;
            g_sel[2 * tok + 1] = i2;
            g_comb[2 * tok]     = 1.f / (1.f + q);
            g_comb[2 * tok + 1] = q / (1.f + q);
            atomicAdd(&s_z2, z * z);
        }
        if (lane < E_EXP) atomicAdd(&s_p[lane], expf(acc[lane] - m) / se);
    }
    __syncthreads();
    if (tid < E_EXP) g_rp[blockIdx.x][tid] = s_p[tid];
    if (tid == 0)    g_rz[blockIdx.x] = s_z2;
}

// ---------------- ordered per-expert rank + fused last-block scan ----------------
__global__ void pos_kernel() {
    __shared__ int warpCnt[8][E_EXP];
    __shared__ int running[E_EXP];
    __shared__ int s_last;
    const int tid  = threadIdx.x;
    const int wid  = tid >> 5;
    const int lane = tid & 31;
    if (tid < E_EXP) running[tid] = 0;
    __syncthreads();

    const int base = blockIdx.x * SPB;
    for (int it = 0; it < SPB / 256; it++) {
        const int s = base + it * 256 + tid;
        const int e = g_sel[s];
        unsigned peers = __match_any_sync(0xffffffffu, e);
        const int rank = __popc(peers & ((1u << lane) - 1u));
        if (lane < E_EXP) warpCnt[wid][lane] = 0;
        __syncwarp();
        if (rank == 0) warpCnt[wid][e] = __popc(peers);
        __syncthreads();
        int off = running[e] + rank;
        for (int w = 0; w < wid; w++) off += warpCnt[w][e];
        g_poslocal[s] = off;
        __syncthreads();
        if (tid < E_EXP) {
            int tot = 0;
            #pragma unroll
            for (int w = 0; w < 8; w++) tot += warpCnt[w][tid];
            running[tid] += tot;
        }
        __syncthreads();
    }
    if (tid < E_EXP) g_blkCnt[blockIdx.x][tid] = running[tid];
    __syncthreads();
    if (tid == 0) {
        __threadfence();
        s_last = (atomicAdd(&g_posDone, 1) == NB - 1) ? 1 : 0;
    }
    __syncthreads();
    if (s_last) {
        if (tid < E_EXP) {
            int run = 0;
            for (int b = 0; b < NB; b++) {
                g_blkOff[b][tid] = run;
                run += g_blkCnt[b][tid];
            }
            g_cnt[tid] = run;
        }
        __syncthreads();
        if (tid == 0) { g_posDone = 0; __threadfence(); }
    }
}

// ---------------- prep: scatter + both weight transposes ----------------
#define SC_BLOCKS 8192
#define UG_BX (TWO_I / 32)
#define UG_BY (D_DIM / 32)
#define UG_BLOCKS (UG_BX * UG_BY * E_EXP)
#define DN_BX (D_DIM / 32)
#define DN_BY (I_DIM / 32)
#define DN_BLOCKS (DN_BX * DN_BY * E_EXP)
#define PREP_BLOCKS (SC_BLOCKS + UG_BLOCKS + DN_BLOCKS)

__global__ __launch_bounds__(256) void prep_kernel(const float* __restrict__ x,
                                                   const float* __restrict__ w_ug,
                                                   const float* __restrict__ w_dn) {
    __shared__ float tile[32][33];
    const int bid = blockIdx.x;
    const int tid = threadIdx.x;

    if (bid < SC_BLOCKS) {
        const int gwarp = (bid * 256 + tid) >> 5;
        const int lane  = tid & 31;
        const int e   = g_sel[gwarp];
        const int pos = g_poslocal[gwarp] + g_blkOff[gwarp / SPB][e];
        int slot = -1;
        if (pos < CAP) {
            slot = e * CAP + pos;
            const float4* src = (const float4*)(x + (size_t)(gwarp >> 1) * D_DIM);
            uint2* dst = (uint2*)(g_xh + (size_t)slot * D_DIM);
            #pragma unroll
            for (int i = 0; i < 8; i++) {
                float4 v = src[lane + 32 * i];
                dst[lane + 32 * i] = make_uint2(pack_h2(v.x, v.y), pack_h2(v.z, v.w));
            }
        }
        if (lane == 0) g_slot[gwarp] = slot;
        return;
    }

    const int tx = tid & 31, ty = tid >> 5;
    if (bid < SC_BLOCKS + UG_BLOCKS) {
        const int t = bid - SC_BLOCKS;
        const int z = t / (UG_BX * UG_BY);
        const int rem = t % (UG_BX * UG_BY);
        const int bx = rem % UG_BX, by = rem / UG_BX;
        const float* S = w_ug + (size_t)z * D_DIM * TWO_I;
        __half* Dp = g_wug_th + (size_t)z * TWO_I * D_DIM;
        const int c0 = bx * 32, r0 = by * 32;
        #pragma unroll
        for (int i = 0; i < 32; i += 8)
            tile[ty + i][tx] = S[(size_t)(r0 + ty + i) * TWO_I + (c0 + tx)];
        __syncthreads();
        #pragma unroll
        for (int i = 0; i < 32; i += 8) {
            const int c = c0 + ty + i;
            int pcol;
            if (c < I_DIM) pcol = 16 * (c >> 3) + (c & 7);
            else { const int j = c - I_DIM; pcol = 16 * (j >> 3) + 8 + (j & 7); }
            Dp[(size_t)pcol * D_DIM + (r0 + tx)] = __float2half_rn(tile[tx][ty + i]);
        }
    } else {
        const int t = bid - SC_BLOCKS - UG_BLOCKS;
        const int z = t / (DN_BX * DN_BY);
        const int rem = t % (DN_BX * DN_BY);
        const int bx = rem % DN_BX, by = rem / DN_BX;
        const float* S = w_dn + (size_t)z * I_DIM * D_DIM;
        __half* Dp = g_wdn_th + (size_t)z * D_DIM * I_DIM;
        const int c0 = bx * 32, r0 = by * 32;
        #pragma unroll
        for (int i = 0; i < 32; i += 8)
            tile[ty + i][tx] = S[(size_t)(r0 + ty + i) * D_DIM + (c0 + tx)];
        __syncthreads();
        #pragma unroll
        for (int i = 0; i < 32; i += 8)
            Dp[(size_t)(c0 + ty + i) * I_DIM + (r0 + tx)] = __float2half_rn(tile[tx][ty + i]);
    }
}

// ---------------- fp16 mma GEMM: CTA 256x128, 512 threads, cp.async 3-stage, K-chunk 64 ----
// (round-13 configuration: the empirical optimum; frozen)
#define SU 36
#define A_TILE_U (256 * SU)
#define B_TILE_U (128 * SU)
#define BUF_U  (A_TILE_U + B_TILE_U)
#define HG_SMEM (3 * BUF_U * 4)           // 165888 bytes

template <int Kdim, int Ndim, int WHICH>
__global__ __launch_bounds__(512, 1)
void hgemm_kernel(const __half* __restrict__ Wt) {
    const int e   = blockIdx.z;
    const int cnt = g_cnt[e];
    const int m0  = blockIdx.y * 256;
    if (m0 >= cnt) return;
    const int n0  = blockIdx.x * 128;

    const __half* __restrict__ Ah = ((WHICH == 1) ? g_xh : g_acth)
                                    + (size_t)e * CAP * Kdim + (size_t)m0 * Kdim;
    const __half* __restrict__ Bh = Wt + (size_t)e * Ndim * Kdim + (size_t)n0 * Kdim;

    extern __shared__ uint32_t smem[];
    const uint32_t smem_base = smem_u32(smem);

    const int tid  = threadIdx.x;
    const int lane = tid & 31;
    const int wid  = tid >> 5;
    const int warp_m = (wid >> 2) * 64;
    const int warp_n = (wid & 3) * 32;
    const int g  = lane >> 2;
    const int t4 = lane & 3;

    float acc[4][4][4];
    #pragma unroll
    for (int i = 0; i < 4; i++)
        #pragma unroll
        for (int j = 0; j < 4; j++)
            #pragma unroll
            for (int q = 0; q < 4; q++) acc[i][j][q] = 0.f;

    const int aSRow = tid >> 1;
    const int aJ0   = (tid & 1) * 4;
    const int bSRow = tid >> 2;
    const int bJ0   = (tid & 3) * 2;

    const int aRow = warp_m + (lane & 15);
    const int aOff = 4 * (lane >> 4);
    const int bRow = warp_n + 8 * ((lane >> 4) & 1) + (lane & 7);
    const int bOff = 4 * ((lane >> 3) & 1);
    const uint32_t aBase = smem_base + (uint32_t)(aRow * SU + aOff) * 4u;
    const uint32_t bBase = smem_base + (uint32_t)(A_TILE_U + bRow * SU + bOff) * 4u;

    const int NC = Kdim / 64;

    #define HG_ISSUE(c_) do {                                                     \
        if ((c_) < NC) {                                                          \
            const uint32_t dstA = smem_base + (uint32_t)(((c_) % 3) * BUF_U) * 4u;\
            const uint32_t dstB = dstA + (uint32_t)A_TILE_U * 4u;                 \
            const int k0_ = (c_) * 64;                                            \
            _Pragma("unroll")                                                     \
            for (int i_ = 0; i_ < 4; i_++) {                                      \
                const int j_ = aJ0 + i_;                                          \
                CP_ASYNC16(dstA + (uint32_t)(aSRow * SU + j_ * 4) * 4u,           \
                           Ah + (size_t)aSRow * Kdim + k0_ + j_ * 8);             \
            }                                                                     \
            _Pragma("unroll")                                                     \
            for (int i_ = 0; i_ < 2; i_++) {                                      \
                const int j_ = bJ0 + i_;                                          \
                CP_ASYNC16(dstB + (uint32_t)(bSRow * SU + j_ * 4) * 4u,           \
                           Bh + (size_t)bSRow * Kdim + k0_ + j_ * 8);             \
            }                                                                     \
        }                                                                         \
        CP_COMMIT();                                                              \
    } while (0)

    HG_ISSUE(0);
    HG_ISSUE(1);

    for (int c = 0; c < NC; c++) {
        CP_WAIT1();
        __syncthreads();
        HG_ISSUE(c + 2);
        const uint32_t bufOff = (uint32_t)((c % 3) * BUF_U) * 4u;

        #pragma unroll
        for (int ks = 0; ks < 4; ks++) {
            uint32_t bf[4][2];
            #pragma unroll
            for (int p = 0; p < 2; p++) {
                LDSM_X4(bf[2 * p][0], bf[2 * p][1], bf[2 * p + 1][0], bf[2 * p + 1][1],
                        bBase + bufOff + (uint32_t)(p * 16 * SU * 4 + ks * 32));
            }
            #pragma unroll
            for (int mf = 0; mf < 4; mf++) {
                uint32_t a0, a1, a2, a3;
                LDSM_X4(a0, a1, a2, a3,
                        aBase + bufOff + (uint32_t)(mf * 16 * SU * 4 + ks * 32));
                #pragma unroll
                for (int nf = 0; nf < 4; nf++)
                    mma_f16(acc[mf][nf], a0, a1, a2, a3, bf[nf][0], bf[nf][1]);
            }
        }
    }

    if (WHICH == 1) {
        __half* Ao = g_acth + (size_t)(e * CAP + m0) * I_DIM;
        #pragma unroll
        for (int mf = 0; mf < 4; mf++) {
            const int row = warp_m + mf * 16 + g;
            #pragma unroll
            for (int pr = 0; pr < 2; pr++) {
                const int j = n0 / 2 + ((wid & 3) * 2 + pr) * 8 + t4 * 2;
                const float* gg = acc[mf][2 * pr];
                const float* uu = acc[mf][2 * pr + 1];
                const float a0 = gg[0] / (1.f + expf(-gg[0])) * uu[0];
                const float a1 = gg[1] / (1.f + expf(-gg[1])) * uu[1];
                const float a2 = gg[2] / (1.f + expf(-gg[2])) * uu[2];
                const float a3 = gg[3] / (1.f + expf(-gg[3])) * uu[3];
                *(uint32_t*)(Ao + (size_t)row * I_DIM + j)       = pack_h2(a0, a1);
                *(uint32_t*)(Ao + (size_t)(row + 8) * I_DIM + j) = pack_h2(a2, a3);
            }
        }
    } else {
        __half* Co = g_eouth + (size_t)(e * CAP + m0) * Ndim + n0;
        #pragma unroll
        for (int mf = 0; mf < 4; mf++) {
            const int row = warp_m + mf * 16 + g;
            #pragma unroll
            for (int nf = 0; nf < 4; nf++) {
                const int col = warp_n + nf * 8 + t4 * 2;
                *(uint32_t*)(Co + (size_t)row * Ndim + col) =
                    pack_h2(acc[mf][nf][0], acc[mf][nf][1]);
                *(uint32_t*)(Co + (size_t)(row + 8) * Ndim + col) =
                    pack_h2(acc[mf][nf][2], acc[mf][nf][3]);
            }
        }
    }
}

// ---------------- gather + combine (fp16 expert outputs, uint4 loads) ----------------
__global__ void gather_kernel(float* __restrict__ out) {
    const int t    = (blockIdx.x * blockDim.x + threadIdx.x) >> 5;
    const int lane = threadIdx.x & 31;
    if (t >= T_TOK) return;
    const int s0 = 2 * t, s1 = s0 + 1;
    const int sl0 = g_slot[s0], sl1 = g_slot[s1];
    const float w0 = g_comb[s0], w1 = g_comb[s1];
    const uint4* r0 = (sl0 >= 0) ? (const uint4*)(g_eouth + (size_t)sl0 * D_DIM) : nullptr;
    const uint4* r1 = (sl1 >= 0) ? (const uint4*)(g_eouth + (size_t)sl1 * D_DIM) : nullptr;
    float4* orow = (float4*)(out + (size_t)t * D_DIM);
    #pragma unroll
    for (int ii = 0; ii < 4; ii++) {
        const int i = lane + 32 * ii;
        float r[8];
        #pragma unroll
        for (int q = 0; q < 8; q++) r[q] = 0.f;
        if (r0) {
            uint4 v = r0[i];
            float2 p0 = __half22float2(*(__half2*)&v.x);
            float2 p1 = __half22float2(*(__half2*)&v.y);
            float2 p2 = __half22float2(*(__half2*)&v.z);
            float2 p3 = __half22float2(*(__half2*)&v.w);
            r[0] += w0 * p0.x; r[1] += w0 * p0.y; r[2] += w0 * p1.x; r[3] += w0 * p1.y;
            r[4] += w0 * p2.x; r[5] += w0 * p2.y; r[6] += w0 * p3.x; r[7] += w0 * p3.y;
        }
        if (r1) {
            uint4 v = r1[i];
            float2 p0 = __half22float2(*(__half2*)&v.x);
            float2 p1 = __half22float2(*(__half2*)&v.y);
            float2 p2 = __half22float2(*(__half2*)&v.z);
            float2 p3 = __half22float2(*(__half2*)&v.w);
            r[0] += w1 * p0.x; r[1] += w1 * p0.y; r[2] += w1 * p1.x; r[3] += w1 * p1.y;
            r[4] += w1 * p2.x; r[5] += w1 * p2.y; r[6] += w1 * p3.x; r[7] += w1 * p3.y;
        }
        orow[2 * i]     = make_float4(r[0], r[1], r[2], r[3]);
        orow[2 * i + 1] = make_float4(r[4], r[5], r[6], r[7]);
    }
}

// ---------------- final scalars ----------------
__global__ __launch_bounds__(256) void finalize_kernel(float* __restrict__ out) {
    __shared__ float sp[16][E_EXP];
    __shared__ float sz[256];
    __shared__ float s_sum[E_EXP];
    const int tid = threadIdx.x;
    const int e = tid & 15, p = tid >> 4;

    float s = 0.f;
    for (int b = p; b < RBLK; b += 16) s += g_rp[b][e];
    sp[p][e] = s;
    float zz = 0.f;
    for (int b = tid; b < RBLK; b += 256) zz += g_rz[b];
    sz[tid] = zz;
    __syncthreads();

    if (tid < E_EXP) {
        float tsum = 0.f;
        #pragma unroll
        for (int p2 = 0; p2 < 16; p2++) tsum += sp[p2][tid];
        s_sum[tid] = tsum;
    }
    if (tid == 16) {
        float t = 0.f;
        for (int i = 0; i < 256; i++) t += sz[i];
        sz[0] = t;
    }
    __syncthreads();

    const size_t base = (size_t)T_TOK * D_DIM;
    if (tid < E_EXP) out[base + tid] = (float)g_cnt[tid];
    if (tid == 0) {
        float total = 0.f;
        #pragma unroll
        for (int ee = 0; ee < E_EXP; ee++) total += (float)g_cnt[ee];
        total = fmaxf(total, 1.f);
        float ent = 0.f, lb = 0.f;
        #pragma unroll
        for (int ee = 0; ee < E_EXP; ee++) {
            float f = (float)g_cnt[ee] / total;
            ent -= f * logf(f + 1e-6f);
            lb  += (f * 2.0f) * (s_sum[ee] / (float)T_TOK);
        }
        lb *= (float)E_EXP;
        out[base + 16] = ent;
        out[base + 17] = lb;
        out[base + 18] = sz[0] / (float)T_TOK;
    }
}

// ---------------- launch ----------------
extern "C" void kernel_launch(void* const* d_in, const int* in_sizes, int n_in,
                              void* d_out, int out_size) {
    const float* x      = (const float*)d_in[0];
    const float* router = (const float*)d_in[1];
    const float* w_ug   = (const float*)d_in[2];
    const float* w_dn   = (const float*)d_in[3];
    float* out = (float*)d_out;

    __half *wug_t = nullptr, *wdn_t = nullptr;
    cudaGetSymbolAddress((void**)&wug_t, g_wug_th);
    cudaGetSymbolAddress((void**)&wdn_t, g_wdn_th);

    static bool attr_done = false;
    if (!attr_done) {
        cudaFuncSetAttribute(router_kernel, cudaFuncAttributeMaxDynamicSharedMemorySize, R_SMEM_BYTES);
        cudaFuncSetAttribute(hgemm_kernel<D_DIM, TWO_I, 1>,
                             cudaFuncAttributeMaxDynamicSharedMemorySize, HG_SMEM);
        cudaFuncSetAttribute(hgemm_kernel<I_DIM, D_DIM, 2>,
                             cudaFuncAttributeMaxDynamicSharedMemorySize, HG_SMEM);
        attr_done = true;
    }

    router_kernel<<<RBLK, 256, R_SMEM_BYTES>>>(x, router);          // 0
    pos_kernel<<<NB, 256>>>();                                      // 1
    prep_kernel<<<PREP_BLOCKS, 256>>>(x, w_ug, w_dn);               // 2
    hgemm_kernel<D_DIM, TWO_I, 1>                                   // 3 (ncu)
        <<<dim3(TWO_I / 128, CAP / 256, E_EXP), 512, HG_SMEM>>>(wug_t);
    hgemm_kernel<I_DIM, D_DIM, 2>                                   // 4
        <<<dim3(D_DIM / 128, CAP / 256, E_EXP), 512, HG_SMEM>>>(wdn_t);
    gather_kernel<<<T_TOK / 8, 256>>>(out);                         // 5
    finalize_kernel<<<1, 256>>>(out);                               // 6
}